// round 9
// baseline (speedup 1.0000x reference)
#include <cuda_runtime.h>
#include <cuda_fp16.h>
#include <math.h>
#include <stdint.h>

// Problem constants
#define Bb     32
#define Dd     64
#define Kk     512
#define DHW    262144        // D*H*W
#define Nn     131072        // B*H*W
#define EPSf   1e-5f
#define NTILES 1024          // 128-row tiles
#define GRID_P 148           // persistent CTAs

// ---------------------------------------------------------------------------
// Helpers
// ---------------------------------------------------------------------------
__device__ __forceinline__ uint32_t smem_to_u32(const void* p) {
    uint32_t a;
    asm("{ .reg .u64 t; cvta.to.shared.u64 t, %1; cvt.u32.u64 %0, t; }" : "=r"(a) : "l"(p));
    return a;
}
__device__ __forceinline__ uint32_t pack_h2(float a, float b) {
    __half2 h = __floats2half2_rn(a, b);
    return *(uint32_t*)&h;
}
// D = A(16x16 f16, row) * B(16x8 f16, col) + D, fp32 accum
__device__ __forceinline__ void mma_f16(float* c, const uint32_t* a, uint32_t b0, uint32_t b1) {
    asm volatile("mma.sync.aligned.m16n8k16.row.col.f32.f16.f16.f32 "
        "{%0,%1,%2,%3}, {%4,%5,%6,%7}, {%8,%9}, {%0,%1,%2,%3};"
        : "+f"(c[0]), "+f"(c[1]), "+f"(c[2]), "+f"(c[3])
        : "r"(a[0]), "r"(a[1]), "r"(a[2]), "r"(a[3]), "r"(b0), "r"(b1));
}
#define CP_ASYNC16(s, g) asm volatile("cp.async.cg.shared.global [%0], [%1], 16;" :: "r"(s), "l"(g))
#define CP_COMMIT()      asm volatile("cp.async.commit_group;" ::: "memory")
#define CP_WAIT0()       asm volatile("cp.async.wait_group 0;" ::: "memory")

// ---------------------------------------------------------------------------
// Scratch
// ---------------------------------------------------------------------------
__device__ float d_ec[Kk];                 // ||e_k||^2 (fp32)
__device__ int   d_counts[Kk];
__device__ float d_sums[Dd * Kk];          // embed sums [D][K]
__device__ float d_scale[Kk];
// codebook hi-fp16 mma-fragments: [ntile(64)][kstep(4)][lane(32)] -> {b0hi, b1hi}
__device__ uint2 g_fragh[8192];

// ---------------------------------------------------------------------------
// Kernel A: zero sums/counts, ||e_k||^2, fp16 codebook fragments
// ---------------------------------------------------------------------------
__global__ void prep_kernel(const float* __restrict__ emb) {
    int t = threadIdx.x;
    int i = blockIdx.x * 512 + t;          // 0..32767
    d_sums[i] = 0.f;

    if (i < 8192) {   // fragment entry i
        int lane = i & 31;
        int ks   = (i >> 5) & 3;
        int nt   = i >> 7;                 // 0..63
        int code = nt * 8 + (lane >> 2);
        int k0   = ks * 16 + (lane & 3) * 2;
        const float* er = emb + code * 64 + k0;
        uint2 f;
        f.x = pack_h2(__ldg(er),     __ldg(er + 1));
        f.y = pack_h2(__ldg(er + 8), __ldg(er + 9));
        g_fragh[i] = f;
    }

    if (blockIdx.x == 0) {
        d_counts[t] = 0;
        const float4* r = (const float4*)(emb + (t << 6));
        float s = 0.f;
#pragma unroll
        for (int j = 0; j < 16; j++) {
            float4 v = __ldg(r + j);
            s += v.x * v.x + v.y * v.y + v.z * v.z + v.w * v.w;
        }
        d_ec[t] = s;
    }
}

// ---------------------------------------------------------------------------
// SMEM layout (bytes)
// ---------------------------------------------------------------------------
#define XLD       132
#define SM_X0     0           // x tile [64 d][132 f32]   33792
#define SM_X1     33792       //                          33792
#define SM_EC     67584       // ec fp32 [512]             2048
#define SM_SR     69632       // sum|x| per row fp32        512
#define SM_QB     70144       // per-quarter best [4][128] 2048
#define SM_QS     72192       // per-quarter second        2048
#define SM_QI     74240       // per-quarter idx           2048
#define SM_SIDX   76288       // winner idx [128]           512
#define SM_FLN    76800       // flagged count               16
#define SM_FLL    76816       // flagged row list [128]     512 (+pad)
#define SM_FBX    77376       // fallback x [16][68] f32   4352 (+pad)
#define SM_SQ     81792       // q staging 128*37 f32     18944
#define SM_FRAGH  100736      // hi fragments             65536
#define SM_TOTAL  166272

// ---------------------------------------------------------------------------
// Kernel B: persistent 1-term fp16 MMA + gap test + rare exact fallback.
//   148 CTAs x 512 threads. Warp = 32 rows x 128 codes.
// ---------------------------------------------------------------------------
__global__ __launch_bounds__(512, 1)
void assign_kernel(const float* __restrict__ x,
                   const float* __restrict__ emb,
                   float* __restrict__ q) {
    extern __shared__ char smem[];
    uint32_t sb = smem_to_u32(smem);
    int tid = threadIdx.x;
    int wid = tid >> 5;
    int lid = tid & 31;
    int grp = lid >> 2;        // 0..7
    int tig = lid & 3;         // 0..3
    int qtr = wid & 3;         // code quarter
    int rws = wid >> 2;        // row set (0..3)

    float* sel  = (float*)(smem + SM_EC);
    float* ssr  = (float*)(smem + SM_SR);
    float* qB   = (float*)(smem + SM_QB);
    float* qS   = (float*)(smem + SM_QS);
    int*   qI   = (int*)(smem + SM_QI);
    int*   sidx = (int*)(smem + SM_SIDX);
    int*   nfl  = (int*)(smem + SM_FLN);
    int*   fll  = (int*)(smem + SM_FLL);
    float* fbx  = (float*)(smem + SM_FBX);
    float* sq   = (float*)(smem + SM_SQ);

    // ---- prologue: fragments + ec + first x tile ----
#pragma unroll
    for (int jj = 0; jj < 8; jj++) {
        int i = tid + jj * 512;
        CP_ASYNC16(sb + SM_FRAGH + i * 16, (const char*)g_fragh + i * 16);
    }
    {
        const float* xb = x + (size_t)(blockIdx.x >> 5) * DHW + ((blockIdx.x & 31) << 7);
#pragma unroll
        for (int jj = 0; jj < 4; jj++) {
            int i = tid + jj * 512;
            int d = i >> 5, r4 = (i & 31) << 2;
            CP_ASYNC16(sb + SM_X0 + (d * XLD + r4) * 4, (const char*)(xb + (d << 12) + r4));
        }
    }
    sel[tid] = d_ec[tid];
    CP_COMMIT();
    CP_WAIT0();
    __syncthreads();

    // ---- persistent tile loop ----
    int j = 0;
    for (int t = blockIdx.x; t < NTILES; t += GRID_P, j++) {
        float* sxc = (float*)(smem + ((j & 1) ? SM_X1 : SM_X0));
        int b   = t >> 5;
        int hw0 = (t & 31) << 7;
        if (tid == 0) *nfl = 0;

        // prefetch next tile into other buffer (overlaps MMA phase)
        int tn = t + GRID_P;
        if (tn < NTILES) {
            const float* xb = x + (size_t)(tn >> 5) * DHW + ((tn & 31) << 7);
            uint32_t dstb = sb + ((j & 1) ? SM_X0 : SM_X1);
#pragma unroll
            for (int jj = 0; jj < 4; jj++) {
                int i = tid + jj * 512;
                int d = i >> 5, r4 = (i & 31) << 2;
                CP_ASYNC16(dstb + (d * XLD + r4) * 4, (const char*)(xb + (d << 12) + r4));
            }
        }
        CP_COMMIT();

        // ---- A fragments (hi only) + per-row sum|x| ----
        uint32_t Ahi[32];
        float sabs[4] = {0.f, 0.f, 0.f, 0.f};
#pragma unroll
        for (int mt = 0; mt < 2; mt++) {
            int rb = rws * 32 + mt * 16 + grp;
#pragma unroll
            for (int ks = 0; ks < 4; ks++) {
                int kb = ks * 16 + tig * 2;
                float v00 = sxc[kb * XLD + rb],           v01 = sxc[(kb + 1) * XLD + rb];
                float v10 = sxc[kb * XLD + rb + 8],       v11 = sxc[(kb + 1) * XLD + rb + 8];
                float v20 = sxc[(kb + 8) * XLD + rb],     v21 = sxc[(kb + 9) * XLD + rb];
                float v30 = sxc[(kb + 8) * XLD + rb + 8], v31 = sxc[(kb + 9) * XLD + rb + 8];
                int o = mt * 16 + ks * 4;
                Ahi[o + 0] = pack_h2(v00, v01);
                Ahi[o + 1] = pack_h2(v10, v11);
                Ahi[o + 2] = pack_h2(v20, v21);
                Ahi[o + 3] = pack_h2(v30, v31);
                sabs[mt * 2]     += fabsf(v00) + fabsf(v01) + fabsf(v20) + fabsf(v21);
                sabs[mt * 2 + 1] += fabsf(v10) + fabsf(v11) + fabsf(v30) + fabsf(v31);
            }
        }
#pragma unroll
        for (int o = 1; o <= 2; o <<= 1) {
#pragma unroll
            for (int v = 0; v < 4; v++) sabs[v] += __shfl_xor_sync(0xffffffffu, sabs[v], o);
        }
        if (qtr == 0 && tig == 0) {
            int rb = rws * 32 + grp;
            ssr[rb]      = sabs[0];
            ssr[rb + 8]  = sabs[1];
            ssr[rb + 16] = sabs[2];
            ssr[rb + 24] = sabs[3];
        }

        // ---- 1-term MMA, track best + second-best per row-chain ----
        float best[4] = {3.4e38f, 3.4e38f, 3.4e38f, 3.4e38f};
        float secv[4] = {3.4e38f, 3.4e38f, 3.4e38f, 3.4e38f};
        int   idx[4]  = {0, 0, 0, 0};

#define UPD(ch, sval, kk) do {                                              \
        if ((sval) < best[ch]) { secv[ch] = best[ch]; best[ch] = (sval); idx[ch] = (kk); } \
        else if ((sval) < secv[ch]) { secv[ch] = (sval); }                  \
    } while (0)

#pragma unroll 2
        for (int np = 0; np < 8; np++) {
            int ntA = (qtr << 4) + 2 * np;
            float acc[4][4] = {{0.f,0.f,0.f,0.f},{0.f,0.f,0.f,0.f},
                               {0.f,0.f,0.f,0.f},{0.f,0.f,0.f,0.f}};
#pragma unroll
            for (int ks = 0; ks < 4; ks++) {
                uint32_t a0 = sb + SM_FRAGH + (((ntA << 2) + ks) * 32 + lid) * 8;
                uint2 bA, bB;
                asm volatile("ld.shared.v2.b32 {%0,%1}, [%2];"
                    : "=r"(bA.x), "=r"(bA.y) : "r"(a0));
                asm volatile("ld.shared.v2.b32 {%0,%1}, [%2];"
                    : "=r"(bB.x), "=r"(bB.y) : "r"(a0 + 1024));
                mma_f16(acc[0], &Ahi[ks * 4],      bA.x, bA.y);
                mma_f16(acc[1], &Ahi[ks * 4],      bB.x, bB.y);
                mma_f16(acc[2], &Ahi[16 + ks * 4], bA.x, bA.y);
                mma_f16(acc[3], &Ahi[16 + ks * 4], bB.x, bB.y);
            }
            int base0 = ntA * 8 + 2 * tig;
            float2 e0 = *(float2*)(sel + base0);
            float2 e1 = *(float2*)(sel + base0 + 8);
            float s;
            s = fmaf(acc[0][0], -2.f, e0.x); UPD(0, s, base0);
            s = fmaf(acc[0][1], -2.f, e0.y); UPD(0, s, base0 + 1);
            s = fmaf(acc[1][0], -2.f, e1.x); UPD(0, s, base0 + 8);
            s = fmaf(acc[1][1], -2.f, e1.y); UPD(0, s, base0 + 9);
            s = fmaf(acc[0][2], -2.f, e0.x); UPD(1, s, base0);
            s = fmaf(acc[0][3], -2.f, e0.y); UPD(1, s, base0 + 1);
            s = fmaf(acc[1][2], -2.f, e1.x); UPD(1, s, base0 + 8);
            s = fmaf(acc[1][3], -2.f, e1.y); UPD(1, s, base0 + 9);
            s = fmaf(acc[2][0], -2.f, e0.x); UPD(2, s, base0);
            s = fmaf(acc[2][1], -2.f, e0.y); UPD(2, s, base0 + 1);
            s = fmaf(acc[3][0], -2.f, e1.x); UPD(2, s, base0 + 8);
            s = fmaf(acc[3][1], -2.f, e1.y); UPD(2, s, base0 + 9);
            s = fmaf(acc[2][2], -2.f, e0.x); UPD(3, s, base0);
            s = fmaf(acc[2][3], -2.f, e0.y); UPD(3, s, base0 + 1);
            s = fmaf(acc[3][2], -2.f, e1.x); UPD(3, s, base0 + 8);
            s = fmaf(acc[3][3], -2.f, e1.y); UPD(3, s, base0 + 9);
        }
#undef UPD

        // quad-group reduce (best, second, idx); codes disjoint across lanes
#pragma unroll
        for (int v = 0; v < 4; v++) {
#pragma unroll
            for (int o = 1; o <= 2; o <<= 1) {
                float ob = __shfl_xor_sync(0xffffffffu, best[v], o);
                float os = __shfl_xor_sync(0xffffffffu, secv[v], o);
                int   oi = __shfl_xor_sync(0xffffffffu, idx[v], o);
                if (ob < best[v] || (ob == best[v] && oi < idx[v])) {
                    secv[v] = fminf(os, best[v]);
                    best[v] = ob; idx[v] = oi;
                } else {
                    secv[v] = fminf(secv[v], ob);
                }
            }
        }
        if (tig == 0) {
            int rl = rws * 32 + grp;
#pragma unroll
            for (int v = 0; v < 4; v++) {
                qB[qtr * 128 + rl + 8 * v] = best[v];
                qS[qtr * 128 + rl + 8 * v] = secv[v];
                qI[qtr * 128 + rl + 8 * v] = idx[v];
            }
        }
        __syncthreads();

        // ---- per-row merge + gap test ----
        if (tid < 128) {
            float bb = qB[tid], ss = qS[tid];
            int   ii = qI[tid];
#pragma unroll
            for (int qq = 1; qq < 4; qq++) {
                float b2 = qB[qq * 128 + tid];
                float s2 = qS[qq * 128 + tid];
                int   i2 = qI[qq * 128 + tid];
                if (b2 < bb) { ss = fminf(s2, bb); bb = b2; ii = i2; }
                else         { ss = fminf(ss, b2); }
            }
            float G = fmaf(6.8e-3f, ssr[tid], fmaf(2e-3f, fabsf(bb), 0.05f));
            if (ss - bb <= G) {
                int p = atomicAdd(nfl, 1);
                fll[p] = tid;
            } else {
                sidx[tid] = ii;
                atomicAdd(&d_counts[ii], 1);
            }
        }
        __syncthreads();

        // ---- exact fp32 fallback: one warp per flagged row ----
        {
            int nf = *nfl;
            for (int i = wid; i < nf; i += 16) {
                int r = fll[i];
                fbx[wid * 68 + lid]      = sxc[lid * XLD + r];
                fbx[wid * 68 + lid + 32] = sxc[(lid + 32) * XLD + r];
                __syncwarp();
                const float4* xf = (const float4*)(fbx + wid * 68);
                float bE = 3.4e38f;
                int   bK = 1 << 20;
#pragma unroll 2
                for (int c = 0; c < 16; c++) {
                    int k = (c << 5) + lid;
                    const float4* ew = (const float4*)(emb + k * 64);
                    float a0 = 0.f, a1 = 0.f, a2 = 0.f, a3 = 0.f;
#pragma unroll
                    for (int jj = 0; jj < 16; jj++) {
                        float4 e4 = __ldg(ew + jj);
                        float4 xv = xf[jj];
                        a0 = fmaf(xv.x, e4.x, a0);
                        a1 = fmaf(xv.y, e4.y, a1);
                        a2 = fmaf(xv.z, e4.z, a2);
                        a3 = fmaf(xv.w, e4.w, a3);
                    }
                    float ex = sel[k] - 2.f * ((a0 + a1) + (a2 + a3));
                    if (ex < bE || (ex == bE && k < bK)) { bE = ex; bK = k; }
                }
#pragma unroll
                for (int o = 16; o > 0; o >>= 1) {
                    float oe = __shfl_xor_sync(0xffffffffu, bE, o);
                    int   ok = __shfl_xor_sync(0xffffffffu, bK, o);
                    if (oe < bE || (oe == bE && ok < bK)) { bE = oe; bK = ok; }
                }
                if (lid == 0) {
                    sidx[r] = bK;
                    atomicAdd(&d_counts[bK], 1);
                }
            }
        }
        __syncthreads();

        // ---- epilogue: coalesced q via staging + fused sums ----
        float* qb = q + (size_t)b * DHW + hw0;
#pragma unroll
        for (int pass = 0; pass < 2; pass++) {
#pragma unroll
            for (int it = 0; it < 2; it++) {
                int item = tid + it * 512;          // 0..1023
                int r = item >> 3, c = item & 7;
                int ki = sidx[r];
                float4 ev = __ldg((const float4*)(emb + ki * 64 + pass * 32 + c * 4));
                float* sp = sq + r * 37 + c * 4;
                sp[0] = ev.x; sp[1] = ev.y; sp[2] = ev.z; sp[3] = ev.w;
            }
            __syncthreads();
#pragma unroll
            for (int it = 0; it < 2; it++) {
                int item = tid + it * 512;
                int dd = item >> 5, g = item & 31;
                int d  = pass * 32 + dd;
                float4 ov;
                ov.x = sq[(4 * g)     * 37 + dd];
                ov.y = sq[(4 * g + 1) * 37 + dd];
                ov.z = sq[(4 * g + 2) * 37 + dd];
                ov.w = sq[(4 * g + 3) * 37 + dd];
                ((float4*)(qb + (d << 12)))[g] = ov;
                int k0 = sidx[4 * g], k1 = sidx[4 * g + 1];
                int k2 = sidx[4 * g + 2], k3 = sidx[4 * g + 3];
                const float* xr = sxc + d * XLD + 4 * g;
                atomicAdd(&d_sums[(d << 9) + k0], xr[0]);
                atomicAdd(&d_sums[(d << 9) + k1], xr[1]);
                atomicAdd(&d_sums[(d << 9) + k2], xr[2]);
                atomicAdd(&d_sums[(d << 9) + k3], xr[3]);
            }
            __syncthreads();
        }

        CP_WAIT0();
        __syncthreads();
    }
}

// ---------------------------------------------------------------------------
// Kernel C: counts EMA -> norm factor (single CTA)
// ---------------------------------------------------------------------------
__device__ __forceinline__ int decode_scalar_int(const int* p) {
    int v = *p;
    if (v >= 0 && v < 1000000) return v;
    return (int)__int_as_float(v);
}

__global__ void norm_kernel(const float* __restrict__ ema_c,
                            const int* __restrict__ counter) {
    __shared__ float wsum[16];
    __shared__ float tot;
    int k = threadIdx.x;

    int   cnt  = decode_scalar_int(counter) + 1;
    float bias = 1.f - (float)pow(0.99, (double)cnt);

    float avg_c = (ema_c[k] * 0.99f + (float)d_counts[k] * 0.01f) / bias;

    float s = avg_c;
#pragma unroll
    for (int o = 16; o > 0; o >>= 1) s += __shfl_xor_sync(0xffffffffu, s, o);
    if ((k & 31) == 0) wsum[k >> 5] = s;
    __syncthreads();
    if (k < 32) {
        float t = (k < 16) ? wsum[k] : 0.f;
#pragma unroll
        for (int o = 8; o > 0; o >>= 1) t += __shfl_xor_sync(0xffffffffu, t, o);
        if (k == 0) tot = t;
    }
    __syncthreads();
    float nn   = tot;
    float norm = (avg_c + EPSf) / (nn + Kk * EPSf) * nn;
    d_scale[k] = 1.f / (bias * norm);
}

// ---------------------------------------------------------------------------
// Kernel D: emit new_weight [K, D]
// ---------------------------------------------------------------------------
__global__ __launch_bounds__(256)
void weight_kernel(const float* __restrict__ ema_e,
                   const float* __restrict__ emb,
                   const int* __restrict__ training,
                   float* __restrict__ w) {
    int j = blockIdx.x * 256 + threadIdx.x;    // over [D, K]
    int d = j >> 9;
    int k = j & 511;

    int tr = decode_scalar_int(training);
    if (tr != 0) {
        float nhe = ema_e[j] * 0.99f + d_sums[j] * 0.01f;
        w[(k << 6) + d] = nhe * d_scale[k];
    } else {
        w[(k << 6) + d] = emb[(k << 6) + d];
    }
}

// ---------------------------------------------------------------------------
extern "C" void kernel_launch(void* const* d_in, const int* in_sizes, int n_in,
                              void* d_out, int out_size) {
    const float* x        = (const float*)d_in[0];
    const float* emb      = (const float*)d_in[1];
    const float* ema_c    = (const float*)d_in[2];
    const float* ema_e    = (const float*)d_in[3];
    const int*   counter  = (const int*)d_in[4];
    const int*   training = (const int*)d_in[5];

    float* out = (float*)d_out;
    float* q   = out;                          // [B, D, H, W]
    float* w   = out + (size_t)Bb * DHW;       // [K, D]

    cudaFuncSetAttribute(assign_kernel, cudaFuncAttributeMaxDynamicSharedMemorySize, SM_TOTAL);

    prep_kernel  <<<64,     512>>>(emb);
    assign_kernel<<<GRID_P, 512, SM_TOTAL>>>(x, emb, q);
    norm_kernel  <<<1,      Kk>>>(ema_c, counter);
    weight_kernel<<<Dd * Kk / 256, 256>>>(ema_e, emb, training, w);
}

// round 10
// speedup vs baseline: 4.5011x; 4.5011x over previous
#include <cuda_runtime.h>
#include <cuda_fp16.h>
#include <math.h>
#include <stdint.h>

// Problem constants
#define Bb     32
#define Dd     64
#define Kk     512
#define DHW    262144        // D*H*W
#define Nn     131072        // B*H*W
#define EPSf   1e-5f
#define NTILES 1024          // 128-row tiles
#define GRID_P 148           // persistent CTAs

// ---------------------------------------------------------------------------
// Helpers
// ---------------------------------------------------------------------------
__device__ __forceinline__ uint32_t smem_to_u32(const void* p) {
    uint32_t a;
    asm("{ .reg .u64 t; cvta.to.shared.u64 t, %1; cvt.u32.u64 %0, t; }" : "=r"(a) : "l"(p));
    return a;
}
// fp16 split of a pair of floats: hi = h2(fp16(a), fp16(b)), lo = h2 of residuals
__device__ __forceinline__ void f16_split2(float a, float b, uint32_t& hi, uint32_t& lo) {
    __half ha = __float2half_rn(a), hb = __float2half_rn(b);
    float  ra = a - __half2float(ha), rb = b - __half2float(hb);
    __half la = __float2half_rn(ra), lb = __float2half_rn(rb);
    __half2 h = __halves2half2(ha, hb), l = __halves2half2(la, lb);
    hi = *(uint32_t*)&h;
    lo = *(uint32_t*)&l;
}
// D = A(16x16 f16, row) * B(16x8 f16, col) + D, fp32 accum
__device__ __forceinline__ void mma_f16(float* c, const uint32_t* a, uint32_t b0, uint32_t b1) {
    asm volatile("mma.sync.aligned.m16n8k16.row.col.f32.f16.f16.f32 "
        "{%0,%1,%2,%3}, {%4,%5,%6,%7}, {%8,%9}, {%0,%1,%2,%3};"
        : "+f"(c[0]), "+f"(c[1]), "+f"(c[2]), "+f"(c[3])
        : "r"(a[0]), "r"(a[1]), "r"(a[2]), "r"(a[3]), "r"(b0), "r"(b1));
}
#define CP_ASYNC16(s, g) asm volatile("cp.async.cg.shared.global [%0], [%1], 16;" :: "r"(s), "l"(g))
#define CP_COMMIT()      asm volatile("cp.async.commit_group;" ::: "memory")
#define CP_WAIT0()       asm volatile("cp.async.wait_group 0;" ::: "memory")

// ---------------------------------------------------------------------------
// Scratch
// ---------------------------------------------------------------------------
__device__ float d_ec[Kk];                 // ||e_k||^2
__device__ int   d_counts[Kk];
__device__ float d_sums[Dd * Kk];          // embed sums [D][K]
// codebook in fp16-split mma-fragment order:
// [ntile(64)][kstep(4)][lane(32)] -> {b0hi, b1hi, b0lo, b1lo}
__device__ uint4 g_frag[8192];

// ---------------------------------------------------------------------------
// Kernel A: zero sums/counts, ||e_k||^2, fp16-split fragment packing
// ---------------------------------------------------------------------------
__global__ void prep_kernel(const float* __restrict__ emb) {
    int t = threadIdx.x;
    int i = blockIdx.x * 512 + t;          // 0..32767
    d_sums[i] = 0.f;

    if (i < 8192) {   // fragment entry i
        int lane = i & 31;
        int ks   = (i >> 5) & 3;
        int nt   = i >> 7;                 // 0..63
        int code = nt * 8 + (lane >> 2);
        int k0   = ks * 16 + (lane & 3) * 2;
        const float* er = emb + code * 64 + k0;
        float v00 = __ldg(er),     v01 = __ldg(er + 1);
        float v10 = __ldg(er + 8), v11 = __ldg(er + 9);
        uint32_t h0, l0, h1, l1;
        f16_split2(v00, v01, h0, l0);
        f16_split2(v10, v11, h1, l1);
        g_frag[i] = make_uint4(h0, h1, l0, l1);
    }

    if (blockIdx.x == 0) {
        d_counts[t] = 0;
        const float4* r = (const float4*)(emb + (t << 6));
        float s = 0.f;
#pragma unroll
        for (int j = 0; j < 16; j++) {
            float4 v = __ldg(r + j);
            s += v.x * v.x + v.y * v.y + v.z * v.z + v.w * v.w;
        }
        d_ec[t] = s;
    }
}

// ---------------------------------------------------------------------------
// SMEM layout (bytes): x tiles [d(64)][132 f32], double buffered
// ---------------------------------------------------------------------------
#define XLD       132
#define SM_X0     0                        // 33792
#define SM_X1     33792                    // 33792
#define SM_EC     67584                    // 2048
#define SM_BEST   69632                    // 4*128 f32 = 2048
#define SM_IDXH   71680                    // 4*128 i32 = 2048
#define SM_SIDX   73728                    // 128 i32 -> 512
#define SM_SQ     74240                    // 128*37 f32 = 18944
#define SM_FRAG   93184                    // 131072
#define SM_TOTAL  224256

// ---------------------------------------------------------------------------
// Kernel B: persistent 3xFP16 mma.sync GEMM, codebook resident in SMEM.
//   148 CTAs x 512 threads. Warp = 32 rows x 128 codes:
//   quarter = wid & 3 (code quarter), rowset = wid >> 2 (32-row set).
// ---------------------------------------------------------------------------
__global__ __launch_bounds__(512, 1)
void assign_kernel(const float* __restrict__ x,
                   const float* __restrict__ emb,
                   float* __restrict__ q) {
    extern __shared__ char smem[];
    uint32_t sb = smem_to_u32(smem);
    int tid = threadIdx.x;
    int wid = tid >> 5;
    int lid = tid & 31;
    int grp = lid >> 2;        // 0..7
    int tig = lid & 3;         // 0..3
    int qtr = wid & 3;         // code quarter
    int rws = wid >> 2;        // row set (0..3), rows [rws*32, rws*32+32)

    float* sec   = (float*)(smem + SM_EC);
    float* sbest = (float*)(smem + SM_BEST);
    int*   sidxh = (int*)(smem + SM_IDXH);
    int*   sidx  = (int*)(smem + SM_SIDX);
    float* sq    = (float*)(smem + SM_SQ);

    // ---- prologue: codebook fragments + ec + first x tile ----
#pragma unroll
    for (int jj = 0; jj < 16; jj++) {
        int i = tid + jj * 512;
        CP_ASYNC16(sb + SM_FRAG + i * 16, (const char*)g_frag + i * 16);
    }
    {
        int t0  = blockIdx.x;
        const float* xb = x + (size_t)(t0 >> 5) * DHW + ((t0 & 31) << 7);
#pragma unroll
        for (int jj = 0; jj < 4; jj++) {
            int i = tid + jj * 512;             // 0..2047
            int d = i >> 5, r4 = (i & 31) << 2;
            CP_ASYNC16(sb + SM_X0 + (d * XLD + r4) * 4,
                       (const char*)(xb + (d << 12) + r4));
        }
    }
    sec[tid] = d_ec[tid];
    CP_COMMIT();
    CP_WAIT0();
    __syncthreads();

    // ---- persistent tile loop ----
    int j = 0;
    for (int t = blockIdx.x; t < NTILES; t += GRID_P, j++) {
        float* sxc = (float*)(smem + ((j & 1) ? SM_X1 : SM_X0));
        int b   = t >> 5;
        int hw0 = (t & 31) << 7;

        // prefetch next tile (overlaps MMA phase)
        int tn = t + GRID_P;
        if (tn < NTILES) {
            const float* xb = x + (size_t)(tn >> 5) * DHW + ((tn & 31) << 7);
            uint32_t dstb = sb + ((j & 1) ? SM_X0 : SM_X1);
#pragma unroll
            for (int jj = 0; jj < 4; jj++) {
                int i = tid + jj * 512;
                int d = i >> 5, r4 = (i & 31) << 2;
                CP_ASYNC16(dstb + (d * XLD + r4) * 4,
                           (const char*)(xb + (d << 12) + r4));
            }
        }
        CP_COMMIT();

        // A fragments: 32 rows (2 m16-tiles), full D=64, fp16 hi+lo
        uint32_t Ahi[32], Alo[32];
#pragma unroll
        for (int mt = 0; mt < 2; mt++) {
            int rb = rws * 32 + mt * 16 + grp;
#pragma unroll
            for (int ks = 0; ks < 4; ks++) {
                int kb = ks * 16 + tig * 2;
                int o  = mt * 16 + ks * 4;
                f16_split2(sxc[kb * XLD + rb],           sxc[(kb + 1) * XLD + rb],
                           Ahi[o + 0], Alo[o + 0]);
                f16_split2(sxc[kb * XLD + rb + 8],       sxc[(kb + 1) * XLD + rb + 8],
                           Ahi[o + 1], Alo[o + 1]);
                f16_split2(sxc[(kb + 8) * XLD + rb],     sxc[(kb + 9) * XLD + rb],
                           Ahi[o + 2], Alo[o + 2]);
                f16_split2(sxc[(kb + 8) * XLD + rb + 8], sxc[(kb + 9) * XLD + rb + 8],
                           Ahi[o + 3], Alo[o + 3]);
            }
        }

        float best[4] = {3.4e38f, 3.4e38f, 3.4e38f, 3.4e38f};
        int   idx[4]  = {0, 0, 0, 0};

#pragma unroll 2
        for (int np = 0; np < 8; np++) {
            int ntA = (qtr << 4) + 2 * np;
            float acc[4][4] = {{0.f,0.f,0.f,0.f},{0.f,0.f,0.f,0.f},
                               {0.f,0.f,0.f,0.f},{0.f,0.f,0.f,0.f}};
#pragma unroll
            for (int ks = 0; ks < 4; ks++) {
                uint32_t a0 = sb + SM_FRAG + ((((ntA << 2) + ks) << 5) + lid) * 16;
                uint4 bA, bB;
                asm volatile("ld.shared.v4.b32 {%0,%1,%2,%3}, [%4];"
                    : "=r"(bA.x), "=r"(bA.y), "=r"(bA.z), "=r"(bA.w) : "r"(a0));
                asm volatile("ld.shared.v4.b32 {%0,%1,%2,%3}, [%4];"
                    : "=r"(bB.x), "=r"(bB.y), "=r"(bB.z), "=r"(bB.w) : "r"(a0 + 2048));
                const uint32_t* ah0 = &Ahi[ks * 4];
                const uint32_t* al0 = &Alo[ks * 4];
                const uint32_t* ah1 = &Ahi[16 + ks * 4];
                const uint32_t* al1 = &Alo[16 + ks * 4];
                mma_f16(acc[0], ah0, bA.x, bA.y);     // hi*hi
                mma_f16(acc[1], ah0, bB.x, bB.y);
                mma_f16(acc[2], ah1, bA.x, bA.y);
                mma_f16(acc[3], ah1, bB.x, bB.y);
                mma_f16(acc[0], ah0, bA.z, bA.w);     // hi*lo
                mma_f16(acc[1], ah0, bB.z, bB.w);
                mma_f16(acc[2], ah1, bA.z, bA.w);
                mma_f16(acc[3], ah1, bB.z, bB.w);
                mma_f16(acc[0], al0, bA.x, bA.y);     // lo*hi
                mma_f16(acc[1], al0, bB.x, bB.y);
                mma_f16(acc[2], al1, bA.x, bA.y);
                mma_f16(acc[3], al1, bB.x, bB.y);
            }
            int base0 = ntA * 8 + 2 * tig;
            float2 e0 = *(float2*)(sec + base0);
            float2 e1 = *(float2*)(sec + base0 + 8);
            float s;
            // acc[0]: rows (grp, grp+8) of mt0, codes base0/base0+1
            s = fmaf(acc[0][0], -2.f, e0.x); if (s < best[0]) { best[0] = s; idx[0] = base0; }
            s = fmaf(acc[0][1], -2.f, e0.y); if (s < best[0]) { best[0] = s; idx[0] = base0 + 1; }
            s = fmaf(acc[0][2], -2.f, e0.x); if (s < best[1]) { best[1] = s; idx[1] = base0; }
            s = fmaf(acc[0][3], -2.f, e0.y); if (s < best[1]) { best[1] = s; idx[1] = base0 + 1; }
            s = fmaf(acc[1][0], -2.f, e1.x); if (s < best[0]) { best[0] = s; idx[0] = base0 + 8; }
            s = fmaf(acc[1][1], -2.f, e1.y); if (s < best[0]) { best[0] = s; idx[0] = base0 + 9; }
            s = fmaf(acc[1][2], -2.f, e1.x); if (s < best[1]) { best[1] = s; idx[1] = base0 + 8; }
            s = fmaf(acc[1][3], -2.f, e1.y); if (s < best[1]) { best[1] = s; idx[1] = base0 + 9; }
            s = fmaf(acc[2][0], -2.f, e0.x); if (s < best[2]) { best[2] = s; idx[2] = base0; }
            s = fmaf(acc[2][1], -2.f, e0.y); if (s < best[2]) { best[2] = s; idx[2] = base0 + 1; }
            s = fmaf(acc[2][2], -2.f, e0.x); if (s < best[3]) { best[3] = s; idx[3] = base0; }
            s = fmaf(acc[2][3], -2.f, e0.y); if (s < best[3]) { best[3] = s; idx[3] = base0 + 1; }
            s = fmaf(acc[3][0], -2.f, e1.x); if (s < best[2]) { best[2] = s; idx[2] = base0 + 8; }
            s = fmaf(acc[3][1], -2.f, e1.y); if (s < best[2]) { best[2] = s; idx[2] = base0 + 9; }
            s = fmaf(acc[3][2], -2.f, e1.x); if (s < best[3]) { best[3] = s; idx[3] = base0 + 8; }
            s = fmaf(acc[3][3], -2.f, e1.y); if (s < best[3]) { best[3] = s; idx[3] = base0 + 9; }
        }

        // quad-group argmin reduce (tie -> lowest index)
#pragma unroll
        for (int v = 0; v < 4; v++) {
#pragma unroll
            for (int o = 1; o <= 2; o <<= 1) {
                float ob = __shfl_xor_sync(0xffffffffu, best[v], o);
                int   oi = __shfl_xor_sync(0xffffffffu, idx[v], o);
                if (ob < best[v] || (ob == best[v] && oi < idx[v])) { best[v] = ob; idx[v] = oi; }
            }
        }
        if (tig == 0) {
            int rl = rws * 32 + grp;
            sbest[qtr * 128 + rl]      = best[0];
            sbest[qtr * 128 + rl + 8]  = best[1];
            sbest[qtr * 128 + rl + 16] = best[2];
            sbest[qtr * 128 + rl + 24] = best[3];
            sidxh[qtr * 128 + rl]      = idx[0];
            sidxh[qtr * 128 + rl + 8]  = idx[1];
            sidxh[qtr * 128 + rl + 16] = idx[2];
            sidxh[qtr * 128 + rl + 24] = idx[3];
        }
        __syncthreads();
        // 4-way merge (quarter indices ascend -> strict < keeps lowest on tie)
        if (tid < 128) {
            float bb = sbest[tid]; int ii = sidxh[tid];
#pragma unroll
            for (int qq = 1; qq < 4; qq++) {
                float b2 = sbest[qq * 128 + tid];
                if (b2 < bb) { bb = b2; ii = sidxh[qq * 128 + tid]; }
            }
            sidx[tid] = ii;
            atomicAdd(&d_counts[ii], 1);
        }
        __syncthreads();

        // ---- epilogue: coalesced q via SMEM transpose staging, 2 d-halves ----
        float* qb = q + (size_t)b * DHW + hw0;
#pragma unroll
        for (int pass = 0; pass < 2; pass++) {
            // phase A: gather winning code rows (line-coalesced) -> stage sq[r][37]
#pragma unroll
            for (int it = 0; it < 2; it++) {
                int item = tid + it * 512;          // 0..1023
                int r = item >> 3, c = item & 7;
                int ki = sidx[r];
                float4 ev = __ldg((const float4*)(emb + ki * 64 + pass * 32 + c * 4));
                float* sp = sq + r * 37 + c * 4;
                sp[0] = ev.x; sp[1] = ev.y; sp[2] = ev.z; sp[3] = ev.w;
            }
            __syncthreads();
            // phase B: coalesced float4 stores + fused EMA sums
#pragma unroll
            for (int it = 0; it < 2; it++) {
                int item = tid + it * 512;          // 0..1023
                int dd = item >> 5, g = item & 31;  // dd 0..31, 4-row group g
                int d  = pass * 32 + dd;
                float4 ov;
                ov.x = sq[(4 * g)     * 37 + dd];
                ov.y = sq[(4 * g + 1) * 37 + dd];
                ov.z = sq[(4 * g + 2) * 37 + dd];
                ov.w = sq[(4 * g + 3) * 37 + dd];
                ((float4*)(qb + (d << 12)))[g] = ov;
                int k0 = sidx[4 * g], k1 = sidx[4 * g + 1];
                int k2 = sidx[4 * g + 2], k3 = sidx[4 * g + 3];
                const float* xr = sxc + d * XLD + 4 * g;
                atomicAdd(&d_sums[(d << 9) + k0], xr[0]);
                atomicAdd(&d_sums[(d << 9) + k1], xr[1]);
                atomicAdd(&d_sums[(d << 9) + k2], xr[2]);
                atomicAdd(&d_sums[(d << 9) + k3], xr[3]);
            }
            __syncthreads();
        }

        CP_WAIT0();
        __syncthreads();
    }
}

// ---------------------------------------------------------------------------
// Kernel C: fused norm + weight. Each CTA redundantly computes the counts-EMA
// normalization (deterministic), then writes its 256-element slice of w.
// ---------------------------------------------------------------------------
__device__ __forceinline__ int decode_scalar_int(const int* p) {
    int v = *p;
    if (v >= 0 && v < 1000000) return v;
    return (int)__int_as_float(v);
}

__global__ __launch_bounds__(256)
void weight_kernel(const float* __restrict__ ema_c,
                   const float* __restrict__ ema_e,
                   const float* __restrict__ emb,
                   const int* __restrict__ counter,
                   const int* __restrict__ training,
                   float* __restrict__ w) {
    __shared__ float savg[Kk];
    __shared__ float wsum[8];
    int tid = threadIdx.x;

    int   cnt  = decode_scalar_int(counter) + 1;
    float bias = 1.f - (float)pow(0.99, (double)cnt);

    // counts EMA for all 512 codes (each thread: 2) + partial sum
    float partial = 0.f;
#pragma unroll
    for (int kk = tid; kk < Kk; kk += 256) {
        float avg = (ema_c[kk] * 0.99f + (float)d_counts[kk] * 0.01f) / bias;
        savg[kk] = avg;
        partial += avg;
    }
#pragma unroll
    for (int o = 16; o > 0; o >>= 1) partial += __shfl_xor_sync(0xffffffffu, partial, o);
    if ((tid & 31) == 0) wsum[tid >> 5] = partial;
    __syncthreads();
    float nn = 0.f;
#pragma unroll
    for (int i = 0; i < 8; i++) nn += wsum[i];   // same order in every thread

    int j = blockIdx.x * 256 + tid;    // over [D, K]
    int d = j >> 9;
    int k = j & 511;

    int tr = decode_scalar_int(training);
    if (tr != 0) {
        float norm = (savg[k] + EPSf) / (nn + Kk * EPSf) * nn;
        float sc   = 1.f / (bias * norm);
        float nhe  = ema_e[j] * 0.99f + d_sums[j] * 0.01f;
        w[(k << 6) + d] = nhe * sc;
    } else {
        w[(k << 6) + d] = emb[(k << 6) + d];
    }
}

// ---------------------------------------------------------------------------
extern "C" void kernel_launch(void* const* d_in, const int* in_sizes, int n_in,
                              void* d_out, int out_size) {
    const float* x        = (const float*)d_in[0];
    const float* emb      = (const float*)d_in[1];
    const float* ema_c    = (const float*)d_in[2];
    const float* ema_e    = (const float*)d_in[3];
    const int*   counter  = (const int*)d_in[4];
    const int*   training = (const int*)d_in[5];

    float* out = (float*)d_out;
    float* q   = out;                          // [B, D, H, W]
    float* w   = out + (size_t)Bb * DHW;       // [K, D]

    cudaFuncSetAttribute(assign_kernel, cudaFuncAttributeMaxDynamicSharedMemorySize, SM_TOTAL);

    prep_kernel  <<<64,     512>>>(emb);
    assign_kernel<<<GRID_P, 512, SM_TOTAL>>>(x, emb, q);
    weight_kernel<<<Dd * Kk / 256, 256>>>(ema_c, ema_e, emb, counter, training, w);
}